// round 13
// baseline (speedup 1.0000x reference)
#include <cuda_runtime.h>
#include <cstdint>

// Correlation: out[n,q,y,x] = (1/C) * sum_c d1[n,c,y,x] * d2pad[n,c,y+dy,x+dx]
// q = (dy+4)*9 + (dx+4). Shapes: N=8, C=256, H=96, W=160. Out (8,81,96,160) f32.
//
// R13: R3 scalar core (384 thr = 3 dy x 128, 4 px/thread) + R12 hoisted
// loaders + channel-split wave smoothing: grid.z=2 halves of C (1440 blocks
// -> 5 waves @97% vs 3 waves @81%), half-1 writes static scratch, combine
// kernel adds. Output scaling applied in both halves (linear).

#define CC   256
#define HH   96
#define WW   160
#define NN   8

constexpr int TQX  = 8;    // float4 x-groups per tile -> 32 px
constexpr int TTY  = 16;   // tile rows
constexpr int KC   = 8;    // channels per smem chunk
constexpr int S1S  = 36;   // s1 row stride (floats)
constexpr int S2S  = 44;   // s2 row stride (floats)
constexpr int S2R  = 18;   // s2 rows (16 + 2)
constexpr int NT   = 384;
constexpr int CHALF = CC / 2;               // 128 channels per z
constexpr int NCH  = CHALF / KC;            // 16 chunks
constexpr int S1_F = KC * TTY * S1S;        // 4608
constexpr int S2_F = KC * S2R * S2S;        // 6336
constexpr int STAGE_F = S1_F + S2_F;        // 10944
constexpr int SMEM_BYTES = 2 * STAGE_F * 4; // 87552
constexpr int CH_STRIDE = HH * WW;

constexpr size_t OUT_ELEMS = (size_t)NN * 81 * HH * WW;  // 9,953,280

__device__ float g_scratch[OUT_ELEMS];

__device__ __forceinline__ void cp16(uint32_t dst, const void* src, bool p) {
    asm volatile("cp.async.cg.shared.global [%0], [%1], 16, %2;\n"
                 :: "r"(dst), "l"(src), "r"(p ? 16 : 0));
}
__device__ __forceinline__ void cp_commit() {
    asm volatile("cp.async.commit_group;\n" ::: "memory");
}
template <int N>
__device__ __forceinline__ void cp_wait() {
    asm volatile("cp.async.wait_group %0;\n" :: "n"(N) : "memory");
}

__global__ __launch_bounds__(NT, 2)
void corr_kernel(const float* __restrict__ d1,
                 const float* __restrict__ d2,
                 float* __restrict__ out)
{
    extern __shared__ float smem[];

    // blockIdx.x = g3 + 3*tile_x ; blockIdx.y = tile_y + 6*n ; blockIdx.z = c-half
    const int g3  = blockIdx.x % 3;
    const int tlx = blockIdx.x / 3;
    const int ty0 = (blockIdx.y % 6) * TTY;
    const int n   = blockIdx.y / 6;
    const int x0  = tlx * (TQX * 4);
    const int ch0 = blockIdx.z * CHALF;

    float* obase = (blockIdx.z == 0) ? out : g_scratch;

    const int t    = threadIdx.x;   // 0..383
    const int tsub = t / 128;       // dy within group
    const int tl   = t % 128;
    const int g    = tl % TQX;      // x-group (4 px)
    const int tyl  = tl / TQX;      // 0..15

    float acc[9][4];
#pragma unroll
    for (int dxi = 0; dxi < 9; dxi++)
#pragma unroll
        for (int p = 0; p < 4; p++) acc[dxi][p] = 0.f;

    const int dy_base = 3 * g3 - 4;
    const int yb      = ty0 + dy_base;
    const float* d1n = d1 + ((size_t)n * CC + ch0) * CH_STRIDE;
    const float* d2n = d2 + ((size_t)n * CC + ch0) * CH_STRIDE;

    const uint32_t smem_u32 = (uint32_t)__cvta_generic_to_shared(smem);

    // ---- hoisted copy slots (R12 style): one d1 + one d2 float4 per channel ----
    const bool ok1 = (t < 128);                 // 128 float4 per d1 channel
    const int  yy1 = (t >> 3) & 15;
    const int  xg1 = t & 7;
    const float* s1p = d1n + (size_t)(ty0 + yy1) * WW + x0 + xg1 * 4;
    const uint32_t dst1 = (uint32_t)((yy1 * S1S + xg1 * 4) * 4);

    const bool v2  = (t < 180);                 // 180 float4 per d2 channel
    const int  rr2 = t / 10;
    const int  xg2 = t % 10;
    const int  gy2 = yb + rr2;
    const int  gx2 = x0 - 4 + xg2 * 4;
    const bool ok2 = v2 && gy2 >= 0 && gy2 < HH && gx2 >= 0 && gx2 + 3 < WW;
    const float* s2p = ok2 ? d2n + (size_t)gy2 * WW + gx2 : d2n;
    const uint32_t dst2 = (uint32_t)((rr2 * S2S + xg2 * 4) * 4);

    auto load_stage = [&](int stage) {
        const uint32_t sb  = smem_u32 + (uint32_t)(stage * (STAGE_F * 4));
        const uint32_t s1b = sb + dst1;
        const uint32_t s2b = sb + (uint32_t)(S1_F * 4) + dst2;
#pragma unroll
        for (int cc = 0; cc < KC; cc++) {
            if (ok1) cp16(s1b + (uint32_t)(cc * (TTY * S1S * 4)), s1p, true);
            if (v2)  cp16(s2b + (uint32_t)(cc * (S2R * S2S * 4)), s2p, ok2);
            s1p += CH_STRIDE;
            s2p += CH_STRIDE;
        }
        cp_commit();
    };

    // ---- pipeline (R3 shape: 2-stage, load-next then wait) ----
    load_stage(0);

    int stage = 0;
    for (int it = 0; it < NCH; it++) {
        if (it + 1 < NCH) {
            load_stage(stage ^ 1);
            cp_wait<1>();
        } else {
            cp_wait<0>();
        }
        __syncthreads();

        const float* s1c = smem + stage * STAGE_F;
        const float* s2c = s1c + S1_F;

#pragma unroll
        for (int c = 0; c < KC; c++) {
            const float4 a = *reinterpret_cast<const float4*>(
                &s1c[(c * TTY + tyl) * S1S + g * 4]);
            float b[12];
#pragma unroll
            for (int k = 0; k < 3; k++) {
                float4 w = *reinterpret_cast<const float4*>(
                    &s2c[(c * S2R + tyl + tsub) * S2S + g * 4 + k * 4]);
                b[k * 4 + 0] = w.x; b[k * 4 + 1] = w.y;
                b[k * 4 + 2] = w.z; b[k * 4 + 3] = w.w;
            }
#pragma unroll
            for (int dxi = 0; dxi < 9; dxi++) {
                acc[dxi][0] = fmaf(a.x, b[dxi + 0], acc[dxi][0]);
                acc[dxi][1] = fmaf(a.y, b[dxi + 1], acc[dxi][1]);
                acc[dxi][2] = fmaf(a.z, b[dxi + 2], acc[dxi][2]);
                acc[dxi][3] = fmaf(a.w, b[dxi + 3], acc[dxi][3]);
            }
        }
        __syncthreads();
        stage ^= 1;
    }

    // ---- epilogue: scale + store partial ----
    const float inv = 1.0f / (float)CC;
    const int y  = ty0 + tyl;
    const int xo = x0 + g * 4;
    const int dy = dy_base + tsub;
#pragma unroll
    for (int dxi = 0; dxi < 9; dxi++) {
        int q = (dy + 4) * 9 + dxi;
        float4 v = make_float4(acc[dxi][0] * inv, acc[dxi][1] * inv,
                               acc[dxi][2] * inv, acc[dxi][3] * inv);
        *reinterpret_cast<float4*>(
            obase + (((size_t)n * 81 + q) * HH + y) * WW + xo) = v;
    }
}

__global__ __launch_bounds__(256)
void combine_kernel(float* __restrict__ out)
{
    const size_t i = ((size_t)blockIdx.x * 256 + threadIdx.x) * 4;
    if (i < OUT_ELEMS) {
        float4 a = *reinterpret_cast<float4*>(out + i);
        float4 b = *reinterpret_cast<const float4*>(g_scratch + i);
        a.x += b.x; a.y += b.y; a.z += b.z; a.w += b.w;
        *reinterpret_cast<float4*>(out + i) = a;
    }
}

extern "C" void kernel_launch(void* const* d_in, const int* in_sizes, int n_in,
                              void* d_out, int out_size)
{
    const float* data1 = (const float*)d_in[0];
    const float* data2 = (const float*)d_in[1];
    float* out = (float*)d_out;

    cudaFuncSetAttribute(corr_kernel,
                         cudaFuncAttributeMaxDynamicSharedMemorySize,
                         SMEM_BYTES);

    dim3 grid(3 * (WW / (TQX * 4)), (HH / TTY) * NN, 2);  // (15, 48, 2)
    dim3 block(NT, 1, 1);
    corr_kernel<<<grid, block, SMEM_BYTES>>>(data1, data2, out);

    const int n4 = (int)(OUT_ELEMS / 4);
    combine_kernel<<<(n4 + 255) / 256, 256>>>(out);
}

// round 14
// speedup vs baseline: 1.0089x; 1.0089x over previous
#include <cuda_runtime.h>
#include <cstdint>

// Correlation: out[n,q,y,x] = (1/C) * sum_c d1[n,c,y,x] * d2pad[n,c,y+dy,x+dx]
// q = (dy+4)*9 + (dx+4). Shapes: N=8, C=256, H=96, W=160. Out (8,81,96,160) f32.
//
// R14: R3 scalar core (384 thr = 3 dy x 128, 4 px/thread, KC=8 2-stage
// cp.async) + hoisted copy slots (R12/R13) as a single full-C launch.
// Last iteration peeled.

#define CC   256
#define HH   96
#define WW   160
#define NN   8

constexpr int TQX  = 8;    // float4 x-groups per tile -> 32 px
constexpr int TTY  = 16;   // tile rows
constexpr int KC   = 8;    // channels per smem chunk
constexpr int S1S  = 36;   // s1 row stride (floats)
constexpr int S2S  = 44;   // s2 row stride (floats)
constexpr int S2R  = 18;   // s2 rows (16 + 2)
constexpr int NT   = 384;
constexpr int NCH  = CC / KC;               // 32 chunks
constexpr int S1_F = KC * TTY * S1S;        // 4608
constexpr int S2_F = KC * S2R * S2S;        // 6336
constexpr int STAGE_F = S1_F + S2_F;        // 10944
constexpr int SMEM_BYTES = 2 * STAGE_F * 4; // 87552
constexpr int CH_STRIDE = HH * WW;

__device__ __forceinline__ void cp16(uint32_t dst, const void* src, bool p) {
    asm volatile("cp.async.cg.shared.global [%0], [%1], 16, %2;\n"
                 :: "r"(dst), "l"(src), "r"(p ? 16 : 0));
}
__device__ __forceinline__ void cp_commit() {
    asm volatile("cp.async.commit_group;\n" ::: "memory");
}
template <int N>
__device__ __forceinline__ void cp_wait() {
    asm volatile("cp.async.wait_group %0;\n" :: "n"(N) : "memory");
}

__global__ __launch_bounds__(NT, 2)
void corr_kernel(const float* __restrict__ d1,
                 const float* __restrict__ d2,
                 float* __restrict__ out)
{
    extern __shared__ float smem[];

    // blockIdx.x = g3 + 3*tile_x ; blockIdx.y = tile_y + 6*n
    const int g3  = blockIdx.x % 3;
    const int tlx = blockIdx.x / 3;
    const int ty0 = (blockIdx.y % 6) * TTY;
    const int n   = blockIdx.y / 6;
    const int x0  = tlx * (TQX * 4);

    const int t    = threadIdx.x;   // 0..383
    const int tsub = t / 128;       // dy within group
    const int tl   = t % 128;
    const int g    = tl % TQX;      // x-group (4 px)
    const int tyl  = tl / TQX;      // 0..15

    float acc[9][4];
#pragma unroll
    for (int dxi = 0; dxi < 9; dxi++)
#pragma unroll
        for (int p = 0; p < 4; p++) acc[dxi][p] = 0.f;

    const int dy_base = 3 * g3 - 4;
    const int yb      = ty0 + dy_base;
    const float* d1n = d1 + (size_t)n * CC * CH_STRIDE;
    const float* d2n = d2 + (size_t)n * CC * CH_STRIDE;

    const uint32_t smem_u32 = (uint32_t)__cvta_generic_to_shared(smem);

    // ---- hoisted copy slots: one d1 + one d2 float4 per channel ----
    const bool ok1 = (t < 128);                 // 128 float4 per d1 channel
    const int  yy1 = (t >> 3) & 15;
    const int  xg1 = t & 7;
    const float* s1p = d1n + (size_t)(ty0 + yy1) * WW + x0 + xg1 * 4;
    const uint32_t dst1 = (uint32_t)((yy1 * S1S + xg1 * 4) * 4);

    const bool v2  = (t < 180);                 // 180 float4 per d2 channel
    const int  rr2 = t / 10;
    const int  xg2 = t % 10;
    const int  gy2 = yb + rr2;
    const int  gx2 = x0 - 4 + xg2 * 4;
    const bool ok2 = v2 && gy2 >= 0 && gy2 < HH && gx2 >= 0 && gx2 + 3 < WW;
    const float* s2p = ok2 ? d2n + (size_t)gy2 * WW + gx2 : d2n;
    const uint32_t dst2 = (uint32_t)((rr2 * S2S + xg2 * 4) * 4);

    auto load_stage = [&](int stage) {
        const uint32_t sb  = smem_u32 + (uint32_t)(stage * (STAGE_F * 4));
        const uint32_t s1b = sb + dst1;
        const uint32_t s2b = sb + (uint32_t)(S1_F * 4) + dst2;
#pragma unroll
        for (int cc = 0; cc < KC; cc++) {
            if (ok1) cp16(s1b + (uint32_t)(cc * (TTY * S1S * 4)), s1p, true);
            if (v2)  cp16(s2b + (uint32_t)(cc * (S2R * S2S * 4)), s2p, ok2);
            s1p += CH_STRIDE;
            s2p += CH_STRIDE;
        }
        cp_commit();
    };

    auto compute_chunk = [&](int stage) {
        const float* s1c = smem + stage * STAGE_F;
        const float* s2c = s1c + S1_F;
#pragma unroll
        for (int c = 0; c < KC; c++) {
            const float4 a = *reinterpret_cast<const float4*>(
                &s1c[(c * TTY + tyl) * S1S + g * 4]);
            float b[12];
#pragma unroll
            for (int k = 0; k < 3; k++) {
                float4 w = *reinterpret_cast<const float4*>(
                    &s2c[(c * S2R + tyl + tsub) * S2S + g * 4 + k * 4]);
                b[k * 4 + 0] = w.x; b[k * 4 + 1] = w.y;
                b[k * 4 + 2] = w.z; b[k * 4 + 3] = w.w;
            }
#pragma unroll
            for (int dxi = 0; dxi < 9; dxi++) {
                acc[dxi][0] = fmaf(a.x, b[dxi + 0], acc[dxi][0]);
                acc[dxi][1] = fmaf(a.y, b[dxi + 1], acc[dxi][1]);
                acc[dxi][2] = fmaf(a.z, b[dxi + 2], acc[dxi][2]);
                acc[dxi][3] = fmaf(a.w, b[dxi + 3], acc[dxi][3]);
            }
        }
    };

    // ---- pipeline: 2-stage, load-next then wait; last iter peeled ----
    load_stage(0);

    int stage = 0;
    for (int it = 0; it < NCH - 1; it++) {
        load_stage(stage ^ 1);
        cp_wait<1>();
        __syncthreads();
        compute_chunk(stage);
        __syncthreads();
        stage ^= 1;
    }
    cp_wait<0>();
    __syncthreads();
    compute_chunk(stage);

    // ---- epilogue: scale + store ----
    const float inv = 1.0f / (float)CC;
    const int y  = ty0 + tyl;
    const int xo = x0 + g * 4;
    const int dy = dy_base + tsub;
#pragma unroll
    for (int dxi = 0; dxi < 9; dxi++) {
        int q = (dy + 4) * 9 + dxi;
        float4 v = make_float4(acc[dxi][0] * inv, acc[dxi][1] * inv,
                               acc[dxi][2] * inv, acc[dxi][3] * inv);
        *reinterpret_cast<float4*>(
            out + (((size_t)n * 81 + q) * HH + y) * WW + xo) = v;
    }
}

extern "C" void kernel_launch(void* const* d_in, const int* in_sizes, int n_in,
                              void* d_out, int out_size)
{
    const float* data1 = (const float*)d_in[0];
    const float* data2 = (const float*)d_in[1];
    float* out = (float*)d_out;

    cudaFuncSetAttribute(corr_kernel,
                         cudaFuncAttributeMaxDynamicSharedMemorySize,
                         SMEM_BYTES);

    dim3 grid(3 * (WW / (TQX * 4)), (HH / TTY) * NN, 1);  // (15, 48)
    dim3 block(NT, 1, 1);
    corr_kernel<<<grid, block, SMEM_BYTES>>>(data1, data2, out);
}

// round 16
// speedup vs baseline: 1.1019x; 1.0921x over previous
#include <cuda_runtime.h>
#include <cstdint>

// Correlation: out[n,q,y,x] = (1/C) * sum_c d1[n,c,y,x] * d2pad[n,c,y+dy,x+dx]
// q = (dy+4)*9 + (dx+4). Shapes: N=8, C=256, H=96, W=160. Out (8,81,96,160) f32.
//
// R16: R15 with the d2 loader coverage bug fixed (1440 float4 per stage ->
// 4 stride-360 slots, not 2). Single barrier per chunk, stride-invariant
// zero-alu loaders, R3 compute core.

#define CC   256
#define HH   96
#define WW   160
#define NN   8

constexpr int TQX  = 8;    // float4 x-groups per tile -> 32 px
constexpr int TTY  = 16;   // tile rows
constexpr int KC   = 8;    // channels per smem chunk
constexpr int S1S  = 36;   // s1 row stride (floats)
constexpr int S2S  = 44;   // s2 row stride (floats)
constexpr int S2R  = 18;   // s2 rows (16 + 2)
constexpr int NT   = 384;
constexpr int NCH  = CC / KC;               // 32 chunks
constexpr int S1_F = KC * TTY * S1S;        // 4608
constexpr int S2_F = KC * S2R * S2S;        // 6336
constexpr int STAGE_F = S1_F + S2_F;        // 10944
constexpr int SMEM_BYTES = 2 * STAGE_F * 4; // 87552
constexpr int CH_STRIDE = HH * WW;          // floats per channel

__device__ __forceinline__ void cp16(uint32_t dst, const void* src, bool p) {
    asm volatile("cp.async.cg.shared.global [%0], [%1], 16, %2;\n"
                 :: "r"(dst), "l"(src), "r"(p ? 16 : 0));
}
__device__ __forceinline__ void cp_commit() {
    asm volatile("cp.async.commit_group;\n" ::: "memory");
}
template <int N>
__device__ __forceinline__ void cp_wait() {
    asm volatile("cp.async.wait_group %0;\n" :: "n"(N) : "memory");
}

__global__ __launch_bounds__(NT, 2)
void corr_kernel(const float* __restrict__ d1,
                 const float* __restrict__ d2,
                 float* __restrict__ out)
{
    extern __shared__ float smem[];

    // blockIdx.x = g3 + 3*tile_x ; blockIdx.y = tile_y + 6*n
    const int g3  = blockIdx.x % 3;
    const int tlx = blockIdx.x / 3;
    const int ty0 = (blockIdx.y % 6) * TTY;
    const int n   = blockIdx.y / 6;
    const int x0  = tlx * (TQX * 4);

    const int t    = threadIdx.x;   // 0..383
    const int tsub = t / 128;       // dy within group
    const int tl   = t % 128;
    const int g    = tl % TQX;      // x-group (4 px)
    const int tyl  = tl / TQX;      // 0..15

    float acc[9][4];
#pragma unroll
    for (int dxi = 0; dxi < 9; dxi++)
#pragma unroll
        for (int p = 0; p < 4; p++) acc[dxi][p] = 0.f;

    const int dy_base = 3 * g3 - 4;
    const int yb      = ty0 + dy_base;
    const float* d1n = d1 + (size_t)n * CC * CH_STRIDE;
    const float* d2n = d2 + (size_t)n * CC * CH_STRIDE;

    const uint32_t smem_u32 = (uint32_t)__cvta_generic_to_shared(smem);

    // ---- stride-invariant copy slots ----
    // d1: 1024 float4/stage, i = t + 384k, k=0..2 (k=2 only t<256).
    //   xg = t&7, yy = (t>>3)&15, cc = t>>7 + 3k.
    const int  xg1 = t & 7;
    const int  yy1 = (t >> 3) & 15;
    const int  cc1 = t >> 7;            // 0..2
    const bool k2_1 = (t < 256);
    const float* s1p = d1n + ((size_t)cc1 * HH + ty0 + yy1) * WW + x0 + xg1 * 4;
    const uint32_t dst1 =
        (uint32_t)(((cc1 * TTY + yy1) * S1S + xg1 * 4) * 4);

    // d2: 1440 float4/stage, i = t + 360k, k=0..3, t<360.
    //   xg = t%10, rr = (t/10)%18, cc = t/180 + 2k (0..7).
    //   Validity depends only on rr/xg -> one predicate for all k.
    const bool v2  = (t < 360);
    const int  xg2 = t % 10;
    const int  rr2 = (t / 10) % S2R;
    const int  cc2 = t / 180;           // 0..1
    const int  gy2 = yb + rr2;
    const int  gx2 = x0 - 4 + xg2 * 4;
    const bool ok2 = v2 && gy2 >= 0 && gy2 < HH && gx2 >= 0 && gx2 + 3 < WW;
    const float* s2p = ok2 ? d2n + ((size_t)cc2 * HH + gy2) * WW + gx2 : d2n;
    const uint32_t dst2 =
        (uint32_t)(S1_F * 4 + ((cc2 * S2R + rr2) * S2S + xg2 * 4) * 4);

    constexpr int D1_PTR_K = 3 * CH_STRIDE;        // floats
    constexpr int D1_DST_K = 3 * TTY * S1S * 4;    // bytes
    constexpr int D2_PTR_K = 2 * CH_STRIDE;        // floats
    constexpr int D2_DST_K = 2 * S2R * S2S * 4;    // bytes

    auto load_stage = [&](int stage) {
        const uint32_t sb = smem_u32 + (uint32_t)(stage * (STAGE_F * 4));
        cp16(sb + dst1, s1p, true);
        cp16(sb + dst1 + D1_DST_K, s1p + D1_PTR_K, true);
        if (k2_1) cp16(sb + dst1 + 2 * D1_DST_K, s1p + 2 * D1_PTR_K, true);
        if (v2) {
            cp16(sb + dst2,                s2p,                ok2);
            cp16(sb + dst2 +     D2_DST_K, s2p +     D2_PTR_K, ok2);
            cp16(sb + dst2 + 2 * D2_DST_K, s2p + 2 * D2_PTR_K, ok2);
            cp16(sb + dst2 + 3 * D2_DST_K, s2p + 3 * D2_PTR_K, ok2);
        }
        s1p += KC * CH_STRIDE;
        s2p += KC * CH_STRIDE;
        cp_commit();
    };

    auto compute_chunk = [&](int stage) {
        const float* s1c = smem + stage * STAGE_F;
        const float* s2c = s1c + S1_F;
#pragma unroll
        for (int c = 0; c < KC; c++) {
            const float4 a = *reinterpret_cast<const float4*>(
                &s1c[(c * TTY + tyl) * S1S + g * 4]);
            float b[12];
#pragma unroll
            for (int k = 0; k < 3; k++) {
                float4 w = *reinterpret_cast<const float4*>(
                    &s2c[(c * S2R + tyl + tsub) * S2S + g * 4 + k * 4]);
                b[k * 4 + 0] = w.x; b[k * 4 + 1] = w.y;
                b[k * 4 + 2] = w.z; b[k * 4 + 3] = w.w;
            }
#pragma unroll
            for (int dxi = 0; dxi < 9; dxi++) {
                acc[dxi][0] = fmaf(a.x, b[dxi + 0], acc[dxi][0]);
                acc[dxi][1] = fmaf(a.y, b[dxi + 1], acc[dxi][1]);
                acc[dxi][2] = fmaf(a.z, b[dxi + 2], acc[dxi][2]);
                acc[dxi][3] = fmaf(a.w, b[dxi + 3], acc[dxi][3]);
            }
        }
    };

    // ---- pipeline: single barrier per chunk ----
    // iter it: wait(chunk it) -> barrier -> prefetch(it+1) -> compute(it).
    // The barrier follows every thread's compute(it-1), so prefetch into the
    // buffer that held chunk it-1 is race-free; cp_wait before the barrier
    // plus the barrier itself makes chunk it visible to all threads.
    load_stage(0);

    for (int it = 0; it < NCH - 1; it++) {
        cp_wait<0>();
        __syncthreads();
        load_stage((it + 1) & 1);
        compute_chunk(it & 1);
    }
    cp_wait<0>();
    __syncthreads();
    compute_chunk((NCH - 1) & 1);

    // ---- epilogue: scale + store ----
    const float inv = 1.0f / (float)CC;
    const int y  = ty0 + tyl;
    const int xo = x0 + g * 4;
    const int dy = dy_base + tsub;
#pragma unroll
    for (int dxi = 0; dxi < 9; dxi++) {
        int q = (dy + 4) * 9 + dxi;
        float4 v = make_float4(acc[dxi][0] * inv, acc[dxi][1] * inv,
                               acc[dxi][2] * inv, acc[dxi][3] * inv);
        *reinterpret_cast<float4*>(
            out + (((size_t)n * 81 + q) * HH + y) * WW + xo) = v;
    }
}

extern "C" void kernel_launch(void* const* d_in, const int* in_sizes, int n_in,
                              void* d_out, int out_size)
{
    const float* data1 = (const float*)d_in[0];
    const float* data2 = (const float*)d_in[1];
    float* out = (float*)d_out;

    cudaFuncSetAttribute(corr_kernel,
                         cudaFuncAttributeMaxDynamicSharedMemorySize,
                         SMEM_BYTES);

    dim3 grid(3 * (WW / (TQX * 4)), (HH / TTY) * NN, 1);  // (15, 48)
    dim3 block(NT, 1, 1);
    corr_kernel<<<grid, block, SMEM_BYTES>>>(data1, data2, out);
}

// round 17
// speedup vs baseline: 1.1131x; 1.0102x over previous
#include <cuda_runtime.h>
#include <cstdint>

// Correlation: out[n,q,y,x] = (1/C) * sum_c d1[n,c,y,x] * d2pad[n,c,y+dy,x+dx]
// q = (dy+4)*9 + (dx+4). Shapes: N=8, C=256, H=96, W=160. Out (8,81,96,160) f32.
//
// R17: R16 pipeline (single barrier/chunk, stride-invariant zero-alu loaders,
// KC=8 2-stage cp.async) + R12 f32x2 compute core (4 px/thread, 18 u64 accs,
// aligned b-pairs free from ulonglong2 loads, 5 odd packs/channel).

#define CC   256
#define HH   96
#define WW   160
#define NN   8

constexpr int TQX  = 8;    // float4 x-groups per tile -> 32 px
constexpr int TTY  = 16;   // tile rows
constexpr int KC   = 8;    // channels per smem chunk
constexpr int S1S  = 36;   // s1 row stride (floats)
constexpr int S2S  = 44;   // s2 row stride (floats)
constexpr int S2R  = 18;   // s2 rows (16 + 2)
constexpr int NT   = 384;
constexpr int NCH  = CC / KC;               // 32 chunks
constexpr int S1_F = KC * TTY * S1S;        // 4608
constexpr int S2_F = KC * S2R * S2S;        // 6336
constexpr int STAGE_F = S1_F + S2_F;        // 10944
constexpr int SMEM_BYTES = 2 * STAGE_F * 4; // 87552
constexpr int CH_STRIDE = HH * WW;          // floats per channel

typedef unsigned long long u64;

__device__ __forceinline__ void cp16(uint32_t dst, const void* src, bool p) {
    asm volatile("cp.async.cg.shared.global [%0], [%1], 16, %2;\n"
                 :: "r"(dst), "l"(src), "r"(p ? 16 : 0));
}
__device__ __forceinline__ void cp_commit() {
    asm volatile("cp.async.commit_group;\n" ::: "memory");
}
template <int N>
__device__ __forceinline__ void cp_wait() {
    asm volatile("cp.async.wait_group %0;\n" :: "n"(N) : "memory");
}
__device__ __forceinline__ u64 pk(float lo, float hi) {
    u64 r;
    asm("mov.b64 %0, {%1, %2};" : "=l"(r) : "f"(lo), "f"(hi));
    return r;
}
__device__ __forceinline__ void upk(u64 v, float& lo, float& hi) {
    asm("mov.b64 {%0, %1}, %2;" : "=f"(lo), "=f"(hi) : "l"(v));
}
__device__ __forceinline__ void fma2(u64& acc, u64 a, u64 b) {
    asm("fma.rn.f32x2 %0, %1, %2, %0;" : "+l"(acc) : "l"(a), "l"(b));
}

__global__ __launch_bounds__(NT, 2)
void corr_kernel(const float* __restrict__ d1,
                 const float* __restrict__ d2,
                 float* __restrict__ out)
{
    extern __shared__ float smem[];

    // blockIdx.x = g3 + 3*tile_x ; blockIdx.y = tile_y + 6*n
    const int g3  = blockIdx.x % 3;
    const int tlx = blockIdx.x / 3;
    const int ty0 = (blockIdx.y % 6) * TTY;
    const int n   = blockIdx.y / 6;
    const int x0  = tlx * (TQX * 4);

    const int t    = threadIdx.x;   // 0..383
    const int tsub = t / 128;       // dy within group
    const int tl   = t % 128;
    const int g    = tl % TQX;      // x-group (4 px)
    const int tyl  = tl / TQX;      // 0..15

    u64 acc[9][2];
#pragma unroll
    for (int dxi = 0; dxi < 9; dxi++) {
        acc[dxi][0] = 0ull;
        acc[dxi][1] = 0ull;
    }

    const int dy_base = 3 * g3 - 4;
    const int yb      = ty0 + dy_base;
    const float* d1n = d1 + (size_t)n * CC * CH_STRIDE;
    const float* d2n = d2 + (size_t)n * CC * CH_STRIDE;

    const uint32_t smem_u32 = (uint32_t)__cvta_generic_to_shared(smem);

    // ---- stride-invariant copy slots (R16) ----
    // d1: 1024 float4/stage, i = t + 384k, k=0..2 (k=2 only t<256).
    const int  xg1 = t & 7;
    const int  yy1 = (t >> 3) & 15;
    const int  cc1 = t >> 7;            // 0..2
    const bool k2_1 = (t < 256);
    const float* s1p = d1n + ((size_t)cc1 * HH + ty0 + yy1) * WW + x0 + xg1 * 4;
    const uint32_t dst1 =
        (uint32_t)(((cc1 * TTY + yy1) * S1S + xg1 * 4) * 4);

    // d2: 1440 float4/stage, i = t + 360k, k=0..3, t<360.
    const bool v2  = (t < 360);
    const int  xg2 = t % 10;
    const int  rr2 = (t / 10) % S2R;
    const int  cc2 = t / 180;           // 0..1
    const int  gy2 = yb + rr2;
    const int  gx2 = x0 - 4 + xg2 * 4;
    const bool ok2 = v2 && gy2 >= 0 && gy2 < HH && gx2 >= 0 && gx2 + 3 < WW;
    const float* s2p = ok2 ? d2n + ((size_t)cc2 * HH + gy2) * WW + gx2 : d2n;
    const uint32_t dst2 =
        (uint32_t)(S1_F * 4 + ((cc2 * S2R + rr2) * S2S + xg2 * 4) * 4);

    constexpr int D1_PTR_K = 3 * CH_STRIDE;        // floats
    constexpr int D1_DST_K = 3 * TTY * S1S * 4;    // bytes
    constexpr int D2_PTR_K = 2 * CH_STRIDE;        // floats
    constexpr int D2_DST_K = 2 * S2R * S2S * 4;    // bytes

    auto load_stage = [&](int stage) {
        const uint32_t sb = smem_u32 + (uint32_t)(stage * (STAGE_F * 4));
        cp16(sb + dst1, s1p, true);
        cp16(sb + dst1 + D1_DST_K, s1p + D1_PTR_K, true);
        if (k2_1) cp16(sb + dst1 + 2 * D1_DST_K, s1p + 2 * D1_PTR_K, true);
        if (v2) {
            cp16(sb + dst2,                s2p,                ok2);
            cp16(sb + dst2 +     D2_DST_K, s2p +     D2_PTR_K, ok2);
            cp16(sb + dst2 + 2 * D2_DST_K, s2p + 2 * D2_PTR_K, ok2);
            cp16(sb + dst2 + 3 * D2_DST_K, s2p + 3 * D2_PTR_K, ok2);
        }
        s1p += KC * CH_STRIDE;
        s2p += KC * CH_STRIDE;
        cp_commit();
    };

    // ---- f32x2 compute core (R12) ----
    auto compute_chunk = [&](int stage) {
        const float* s1c = smem + stage * STAGE_F;
        const float* s2c = s1c + S1_F;
#pragma unroll
        for (int c = 0; c < KC; c++) {
            const ulonglong2 A = *reinterpret_cast<const ulonglong2*>(
                &s1c[(c * TTY + tyl) * S1S + g * 4]);
            const u64 ap[2] = {A.x, A.y};

            const float* brow = &s2c[(c * S2R + tyl + tsub) * S2S + g * 4];
            const ulonglong2 B0 = *reinterpret_cast<const ulonglong2*>(brow);
            const ulonglong2 B1 = *reinterpret_cast<const ulonglong2*>(brow + 4);
            const ulonglong2 B2 = *reinterpret_cast<const ulonglong2*>(brow + 8);
            const u64 e[6] = {B0.x, B0.y, B1.x, B1.y, B2.x, B2.y};
            u64 o[5];
#pragma unroll
            for (int k = 0; k < 5; k++) {
                float l0, h0, l1, h1;
                upk(e[k], l0, h0);
                upk(e[k + 1], l1, h1);
                o[k] = pk(h0, l1);
            }
#pragma unroll
            for (int dxi = 0; dxi < 9; dxi++) {
#pragma unroll
                for (int pp = 0; pp < 2; pp++) {
                    const int idx = dxi + 2 * pp;   // 0..10
                    const u64 bb = (idx & 1) ? o[idx >> 1] : e[idx >> 1];
                    fma2(acc[dxi][pp], ap[pp], bb);
                }
            }
        }
    };

    // ---- pipeline: single barrier per chunk (R16) ----
    load_stage(0);

    for (int it = 0; it < NCH - 1; it++) {
        cp_wait<0>();
        __syncthreads();
        load_stage((it + 1) & 1);
        compute_chunk(it & 1);
    }
    cp_wait<0>();
    __syncthreads();
    compute_chunk((NCH - 1) & 1);

    // ---- epilogue ----
    const float inv = 1.0f / (float)CC;
    const int y  = ty0 + tyl;
    const int xo = x0 + g * 4;
    const int dy = dy_base + tsub;
#pragma unroll
    for (int dxi = 0; dxi < 9; dxi++) {
        const int q = (dy + 4) * 9 + dxi;
        float f0, f1, f2, f3;
        upk(acc[dxi][0], f0, f1);
        upk(acc[dxi][1], f2, f3);
        *reinterpret_cast<float4*>(
            out + (((size_t)n * 81 + q) * HH + y) * WW + xo) =
            make_float4(f0 * inv, f1 * inv, f2 * inv, f3 * inv);
    }
}

extern "C" void kernel_launch(void* const* d_in, const int* in_sizes, int n_in,
                              void* d_out, int out_size)
{
    const float* data1 = (const float*)d_in[0];
    const float* data2 = (const float*)d_in[1];
    float* out = (float*)d_out;

    cudaFuncSetAttribute(corr_kernel,
                         cudaFuncAttributeMaxDynamicSharedMemorySize,
                         SMEM_BYTES);

    dim3 grid(3 * (WW / (TQX * 4)), (HH / TTY) * NN, 1);  // (15, 48)
    dim3 block(NT, 1, 1);
    corr_kernel<<<grid, block, SMEM_BYTES>>>(data1, data2, out);
}